// round 2
// baseline (speedup 1.0000x reference)
#include <cuda_runtime.h>
#include <cuda_bf16.h>
#include <math.h>

#define N_SPK 1024
#define M_UTT 20
#define D_DIM 768
#define NM    (N_SPK * M_UTT)   // 20480

// ---- scratch (static device globals; no allocation in kernel_launch) ----
__device__ __nv_bfloat16 g_e[(size_t)NM * D_DIM];      // normalized e, row r = m*N + i
__device__ __nv_bfloat16 g_c[(size_t)N_SPK * D_DIM];   // normalized centroids
__device__ float         g_S[(size_t)N_SPK * NM];      // sims, S[j][m*N + i]  (80 MB)
__device__ double        g_acc;                        // logp accumulator

// ---------------------------------------------------------------- reductions
__device__ __forceinline__ float block_reduce_sum(float v, float* red) {
    int t = threadIdx.x;
    #pragma unroll
    for (int o = 16; o; o >>= 1) v += __shfl_down_sync(0xffffffffu, v, o);
    if ((t & 31) == 0) red[t >> 5] = v;
    __syncthreads();
    if (t < 32) {
        float x = (t < (int)(blockDim.x >> 5)) ? red[t] : 0.0f;
        #pragma unroll
        for (int o = 16; o; o >>= 1) x += __shfl_down_sync(0xffffffffu, x, o);
        if (t == 0) red[0] = x;
    }
    __syncthreads();
    float r = red[0];
    __syncthreads();
    return r;
}

__device__ __forceinline__ float block_reduce_max(float v, float* red) {
    int t = threadIdx.x;
    #pragma unroll
    for (int o = 16; o; o >>= 1) v = fmaxf(v, __shfl_down_sync(0xffffffffu, v, o));
    if ((t & 31) == 0) red[t >> 5] = v;
    __syncthreads();
    if (t < 32) {
        float x = (t < (int)(blockDim.x >> 5)) ? red[t] : -INFINITY;
        #pragma unroll
        for (int o = 16; o; o >>= 1) x = fmaxf(x, __shfl_down_sync(0xffffffffu, x, o));
        if (t == 0) red[0] = x;
    }
    __syncthreads();
    float r = red[0];
    __syncthreads();
    return r;
}

// ------------------------------------------------------------ normalize e
// 20480 blocks x 256 threads; block r handles output row r = m*N + i
__global__ void norm_e_kernel(const float* __restrict__ emb) {
    __shared__ float red[32];
    int r = blockIdx.x;
    int i = r & (N_SPK - 1);
    int m = r >> 10;                       // N_SPK = 1024
    const float* src = emb + ((size_t)i * M_UTT + m) * D_DIM;
    int t = threadIdx.x;
    float v[3]; float ss = 0.0f;
    #pragma unroll
    for (int k = 0; k < 3; k++) { v[k] = src[t + k * 256]; ss += v[k] * v[k]; }
    float tot = block_reduce_sum(ss, red);
    float inv = 1.0f / fmaxf(sqrtf(tot), 1e-8f);
    __nv_bfloat16* dst = g_e + (size_t)r * D_DIM;
    #pragma unroll
    for (int k = 0; k < 3; k++) dst[t + k * 256] = __float2bfloat16(v[k] * inv);
}

// ------------------------------------------------------------ centroids
// 1024 blocks x 256 threads
__global__ void centroid_kernel(const float* __restrict__ emb) {
    __shared__ float red[32];
    int j = blockIdx.x;
    int t = threadIdx.x;
    const float* base = emb + (size_t)j * M_UTT * D_DIM;
    float v[3] = {0.0f, 0.0f, 0.0f};
    for (int m = 0; m < M_UTT; m++) {
        #pragma unroll
        for (int k = 0; k < 3; k++) v[k] += base[(size_t)m * D_DIM + t + k * 256];
    }
    float ss = 0.0f;
    #pragma unroll
    for (int k = 0; k < 3; k++) { v[k] *= (1.0f / M_UTT); ss += v[k] * v[k]; }
    float tot = block_reduce_sum(ss, red);
    float inv = 1.0f / fmaxf(sqrtf(tot), 1e-8f);
    __nv_bfloat16* dst = g_c + (size_t)j * D_DIM;
    #pragma unroll
    for (int k = 0; k < 3; k++) dst[t + k * 256] = __float2bfloat16(v[k] * inv);
}

// ------------------------------------------------------------ GEMM
// S = C (1024 x 768) * E^T (768 x 20480), fp32 accumulate, bf16 operands.
#define BM 128
#define BN 128
#define BK 32
#define TM 8
#define TN 8

__global__ __launch_bounds__(256) void gemm_kernel() {
    __shared__ float As[BK][BM];
    __shared__ float Bs[BK][BN];

    int tid = threadIdx.x;
    int jb = blockIdx.y * BM;     // j (row) block
    int nb = blockIdx.x * BN;     // col block (m*N + i)
    int tx = tid & 15;
    int ty = tid >> 4;

    const __nv_bfloat16* Ag = g_c + (size_t)jb * D_DIM;
    const __nv_bfloat16* Bg = g_e + (size_t)nb * D_DIM;

    float acc[TM][TN];
    #pragma unroll
    for (int a = 0; a < TM; a++)
        #pragma unroll
        for (int b = 0; b < TN; b++) acc[a][b] = 0.0f;

    for (int k0 = 0; k0 < D_DIM; k0 += BK) {
        // each thread loads 16 bf16 from A and 16 from B as 4x uint2 (4 bf16 each)
        #pragma unroll
        for (int c = 0; c < 4; c++) {
            int l   = tid * 4 + c * 1024;
            int row = l >> 5;
            int kk  = l & 31;
            {
                const __nv_bfloat16* pa = Ag + (size_t)row * D_DIM + k0 + kk;
                uint2 u = *reinterpret_cast<const uint2*>(pa);
                __nv_bfloat162 p0 = *reinterpret_cast<__nv_bfloat162*>(&u.x);
                __nv_bfloat162 p1 = *reinterpret_cast<__nv_bfloat162*>(&u.y);
                float2 f0 = __bfloat1622float2(p0);
                float2 f1 = __bfloat1622float2(p1);
                As[kk + 0][row] = f0.x; As[kk + 1][row] = f0.y;
                As[kk + 2][row] = f1.x; As[kk + 3][row] = f1.y;
            }
            {
                const __nv_bfloat16* pb = Bg + (size_t)row * D_DIM + k0 + kk;
                uint2 u = *reinterpret_cast<const uint2*>(pb);
                __nv_bfloat162 p0 = *reinterpret_cast<__nv_bfloat162*>(&u.x);
                __nv_bfloat162 p1 = *reinterpret_cast<__nv_bfloat162*>(&u.y);
                float2 f0 = __bfloat1622float2(p0);
                float2 f1 = __bfloat1622float2(p1);
                Bs[kk + 0][row] = f0.x; Bs[kk + 1][row] = f0.y;
                Bs[kk + 2][row] = f1.x; Bs[kk + 3][row] = f1.y;
            }
        }
        __syncthreads();

        #pragma unroll
        for (int kk = 0; kk < BK; kk++) {
            float a[TM], b[TN];
            #pragma unroll
            for (int ii = 0; ii < TM; ii++) a[ii] = As[kk][ty * TM + ii];
            #pragma unroll
            for (int jj = 0; jj < TN; jj++) b[jj] = Bs[kk][tx * TN + jj];
            #pragma unroll
            for (int ii = 0; ii < TM; ii++)
                #pragma unroll
                for (int jj = 0; jj < TN; jj++)
                    acc[ii][jj] = fmaf(a[ii], b[jj], acc[ii][jj]);
        }
        __syncthreads();
    }

    // store: vectorized float4
    #pragma unroll
    for (int ii = 0; ii < TM; ii++) {
        size_t base = (size_t)(jb + ty * TM + ii) * NM + nb + tx * TN;
        float4* p = reinterpret_cast<float4*>(&g_S[base]);
        p[0] = make_float4(acc[ii][0], acc[ii][1], acc[ii][2], acc[ii][3]);
        p[1] = make_float4(acc[ii][4], acc[ii][5], acc[ii][6], acc[ii][7]);
    }
}

// ------------------------------------------------------------ loss
__global__ void zero_kernel() { g_acc = 0.0; }

// 20480 blocks x 256 threads; block r: row r = m*N + j, softmax over i (1024)
__global__ void loss_kernel(const float* __restrict__ wp, const float* __restrict__ bp) {
    __shared__ float red[32];
    int r = blockIdx.x;
    int m = r >> 10;
    int j = r & (N_SPK - 1);
    const float* row = g_S + (size_t)j * NM + (size_t)m * N_SPK;
    float w = *wp, b = *bp;
    int t = threadIdx.x;

    float v[4];
    float mx = -INFINITY;
    #pragma unroll
    for (int k = 0; k < 4; k++) {
        v[k] = fmaf(w, row[t + k * 256], b);
        mx = fmaxf(mx, v[k]);
    }
    float gmax = block_reduce_max(mx, red);
    float s = 0.0f;
    #pragma unroll
    for (int k = 0; k < 4; k++) s += expf(v[k] - gmax);
    float gsum = block_reduce_sum(s, red);

    if (t == 0) {
        float lse  = gmax + logf(gsum);
        int   tgt  = r / M_UTT;                 // labels[r] = r // M
        float logp = fmaf(w, row[tgt], b) - lse;
        atomicAdd(&g_acc, (double)logp);
    }
}

__global__ void final_kernel(float* out) {
    out[0] = (float)(-g_acc / (double)NM);
}

// ---------------------------------------------------------------- launch
extern "C" void kernel_launch(void* const* d_in, const int* in_sizes, int n_in,
                              void* d_out, int out_size) {
    const float* emb = (const float*)d_in[0];
    const float* w   = (const float*)d_in[1];
    const float* b   = (const float*)d_in[2];
    float* out = (float*)d_out;

    zero_kernel<<<1, 1>>>();
    norm_e_kernel<<<NM, 256>>>(emb);
    centroid_kernel<<<N_SPK, 256>>>(emb);
    dim3 ggrid(NM / BN, N_SPK / BM);   // 160 x 8
    gemm_kernel<<<ggrid, 256>>>();
    loss_kernel<<<NM, 256>>>(w, b);
    final_kernel<<<1, 1>>>(out);
}

// round 4
// speedup vs baseline: 5.2948x; 5.2948x over previous
#include <cuda_runtime.h>
#include <cuda_bf16.h>
#include <cstdint>
#include <math.h>

#define N_SPK 1024
#define M_UTT 20
#define D_DIM 768
#define NM    (N_SPK * M_UTT)   // 20480

// ---- scratch (static device globals; no allocation in kernel_launch) ----
__device__ __nv_bfloat16 g_e[(size_t)NM * D_DIM];      // normalized e, row r = m*N + i
__device__ __nv_bfloat16 g_c[(size_t)N_SPK * D_DIM];   // normalized centroids
__device__ float         g_S[(size_t)N_SPK * NM];      // sims, S[j][m*N + i]  (80 MB)
__device__ double        g_acc;                        // logp accumulator

// =================================================================== PTX utils
__device__ __forceinline__ uint32_t smem_u32(const void* p) {
    uint32_t a;
    asm("{ .reg .u64 t; cvta.to.shared.u64 t, %1; cvt.u32.u64 %0, t; }" : "=r"(a) : "l"(p));
    return a;
}
__device__ __forceinline__ void cp16(uint32_t saddr, const void* gptr) {
    asm volatile("cp.async.cg.shared.global [%0], [%1], 16;" :: "r"(saddr), "l"(gptr));
}
__device__ __forceinline__ void cp_commit() {
    asm volatile("cp.async.commit_group;" ::: "memory");
}
template <int N>
__device__ __forceinline__ void cp_wait() {
    asm volatile("cp.async.wait_group %0;" :: "n"(N) : "memory");
}
__device__ __forceinline__ void ldsm_x4(uint32_t& r0, uint32_t& r1, uint32_t& r2, uint32_t& r3,
                                        uint32_t addr) {
    asm volatile("ldmatrix.sync.aligned.m8n8.x4.shared.b16 {%0,%1,%2,%3}, [%4];"
                 : "=r"(r0), "=r"(r1), "=r"(r2), "=r"(r3) : "r"(addr));
}
__device__ __forceinline__ void ldsm_x2(uint32_t& r0, uint32_t& r1, uint32_t addr) {
    asm volatile("ldmatrix.sync.aligned.m8n8.x2.shared.b16 {%0,%1}, [%2];"
                 : "=r"(r0), "=r"(r1) : "r"(addr));
}
__device__ __forceinline__ void mma16816(float* d, const uint32_t* a, const uint32_t* b) {
    asm volatile(
        "mma.sync.aligned.m16n8k16.row.col.f32.bf16.bf16.f32 "
        "{%0,%1,%2,%3}, {%4,%5,%6,%7}, {%8,%9}, {%0,%1,%2,%3};"
        : "+f"(d[0]), "+f"(d[1]), "+f"(d[2]), "+f"(d[3])
        : "r"(a[0]), "r"(a[1]), "r"(a[2]), "r"(a[3]), "r"(b[0]), "r"(b[1]));
}

// ---------------------------------------------------------------- reductions
__device__ __forceinline__ float block_reduce_sum(float v, float* red) {
    int t = threadIdx.x;
    #pragma unroll
    for (int o = 16; o; o >>= 1) v += __shfl_down_sync(0xffffffffu, v, o);
    if ((t & 31) == 0) red[t >> 5] = v;
    __syncthreads();
    if (t < 32) {
        float x = (t < (int)(blockDim.x >> 5)) ? red[t] : 0.0f;
        #pragma unroll
        for (int o = 16; o; o >>= 1) x += __shfl_down_sync(0xffffffffu, x, o);
        if (t == 0) red[0] = x;
    }
    __syncthreads();
    float r = red[0];
    __syncthreads();
    return r;
}

// ------------------------------------------------------------ normalize e
__global__ void norm_e_kernel(const float* __restrict__ emb) {
    __shared__ float red[32];
    int r = blockIdx.x;
    int i = r & (N_SPK - 1);
    int m = r >> 10;
    const float* src = emb + ((size_t)i * M_UTT + m) * D_DIM;
    int t = threadIdx.x;
    float v[3]; float ss = 0.0f;
    #pragma unroll
    for (int k = 0; k < 3; k++) { v[k] = src[t + k * 256]; ss += v[k] * v[k]; }
    float tot = block_reduce_sum(ss, red);
    float inv = 1.0f / fmaxf(sqrtf(tot), 1e-8f);
    __nv_bfloat16* dst = g_e + (size_t)r * D_DIM;
    #pragma unroll
    for (int k = 0; k < 3; k++) dst[t + k * 256] = __float2bfloat16(v[k] * inv);
}

// ------------------------------------------------------------ centroids
__global__ void centroid_kernel(const float* __restrict__ emb) {
    __shared__ float red[32];
    int j = blockIdx.x;
    int t = threadIdx.x;
    const float* base = emb + (size_t)j * M_UTT * D_DIM;
    float v[3] = {0.0f, 0.0f, 0.0f};
    for (int m = 0; m < M_UTT; m++) {
        #pragma unroll
        for (int k = 0; k < 3; k++) v[k] += base[(size_t)m * D_DIM + t + k * 256];
    }
    float ss = 0.0f;
    #pragma unroll
    for (int k = 0; k < 3; k++) { v[k] *= (1.0f / M_UTT); ss += v[k] * v[k]; }
    float tot = block_reduce_sum(ss, red);
    float inv = 1.0f / fmaxf(sqrtf(tot), 1e-8f);
    __nv_bfloat16* dst = g_c + (size_t)j * D_DIM;
    #pragma unroll
    for (int k = 0; k < 3; k++) dst[t + k * 256] = __float2bfloat16(v[k] * inv);
}

// ------------------------------------------------------------ mma.sync GEMM
// S = C (1024x768) * E^T (768x20480). CTA 128x128, BK=64, 8 warps (4m x 2n),
// warp tile 32x64. Smem rows are 128B with XOR-8 swizzle; double-buffered cp.async.
#define BK        64
#define NKC       (D_DIM / BK)          // 12
#define A_BYTES   (128 * 128)           // 16 KB
#define STAGE_B   (2 * A_BYTES)         // 32 KB (A + B)
#define SMEM_GEMM (2 * STAGE_B)         // 64 KB

__device__ __forceinline__ void load_chunk(uint32_t sb, int st, int kc, int jb, int nb, int tid) {
    uint32_t base = sb + st * STAGE_B;
    const int k0 = kc * BK;
    #pragma unroll
    for (int q = 0; q < 4; q++) {
        int idx = tid + q * 256;        // 0..1023
        int r = idx >> 3, c = idx & 7;
        cp16(base + r * 128 + ((c ^ (r & 7)) << 4),
             g_c + (size_t)(jb + r) * D_DIM + k0 + c * 8);
    }
    base += A_BYTES;
    #pragma unroll
    for (int q = 0; q < 4; q++) {
        int idx = tid + q * 256;
        int r = idx >> 3, c = idx & 7;
        cp16(base + r * 128 + ((c ^ (r & 7)) << 4),
             g_e + (size_t)(nb + r) * D_DIM + k0 + c * 8);
    }
}

__global__ void __launch_bounds__(256) gemm_mma_kernel() {
    extern __shared__ __align__(1024) char smc[];
    uint32_t sb = smem_u32(smc);
    const int tid  = threadIdx.x;
    const int lane = tid & 31;
    const int wid  = tid >> 5;
    const int wm   = wid & 3;           // 4 warps along m (32 rows each)
    const int wn   = wid >> 2;          // 2 warps along n (64 cols each)
    const int jb   = blockIdx.y * 128;
    const int nb   = blockIdx.x * 128;

    float acc[2][8][4];
    #pragma unroll
    for (int mf = 0; mf < 2; mf++)
        #pragma unroll
        for (int nf = 0; nf < 8; nf++)
            #pragma unroll
            for (int q = 0; q < 4; q++) acc[mf][nf][q] = 0.0f;

    // per-lane ldmatrix address components
    const int a_row = wm * 32 + (lane & 15);          // + mf*16
    const int a_hi  = lane >> 4;                      // k-chunk selector
    const int b_row = wn * 64 + (lane & 7);           // + nf*8
    const int b_hi  = (lane >> 3) & 1;
    const int sw    = lane & 7;                       // swizzle key = row & 7

    load_chunk(sb, 0, 0, jb, nb, tid);
    cp_commit();

    #pragma unroll 1
    for (int kc = 0; kc < NKC; kc++) {
        if (kc + 1 < NKC) {
            load_chunk(sb, (kc + 1) & 1, kc + 1, jb, nb, tid);
            cp_commit();
            cp_wait<1>();
        } else {
            cp_wait<0>();
        }
        __syncthreads();

        uint32_t Ab = sb + (kc & 1) * STAGE_B;
        uint32_t Bb = Ab + A_BYTES;
        #pragma unroll
        for (int ks = 0; ks < 4; ks++) {
            uint32_t a[2][4];
            #pragma unroll
            for (int mf = 0; mf < 2; mf++) {
                uint32_t addr = Ab + (a_row + mf * 16) * 128 + (((ks * 2 + a_hi) ^ sw) << 4);
                ldsm_x4(a[mf][0], a[mf][1], a[mf][2], a[mf][3], addr);
            }
            #pragma unroll
            for (int nf = 0; nf < 8; nf++) {
                uint32_t b[2];
                uint32_t addr = Bb + (b_row + nf * 8) * 128 + (((ks * 2 + b_hi) ^ sw) << 4);
                ldsm_x2(b[0], b[1], addr);
                #pragma unroll
                for (int mf = 0; mf < 2; mf++) mma16816(acc[mf][nf], a[mf], b);
            }
        }
        __syncthreads();   // all warps done with this stage before it is overwritten
    }

    // epilogue: direct stores; lane l holds rows (l/4, l/4+8), cols 2*(l%4)+{0,1}
    const int er = lane >> 2;
    const int ec = (lane & 3) * 2;
    #pragma unroll
    for (int mf = 0; mf < 2; mf++) {
        #pragma unroll
        for (int nf = 0; nf < 8; nf++) {
            size_t row0 = (size_t)(jb + wm * 32 + mf * 16 + er) * NM + nb + wn * 64 + nf * 8 + ec;
            *reinterpret_cast<float2*>(g_S + row0)            = make_float2(acc[mf][nf][0], acc[mf][nf][1]);
            *reinterpret_cast<float2*>(g_S + row0 + 8 * (size_t)NM) = make_float2(acc[mf][nf][2], acc[mf][nf][3]);
        }
    }
}

// ------------------------------------------------------------ loss
__global__ void zero_kernel() { g_acc = 0.0; }

// 20480 blocks x 256 threads; block r: row r = m*N + j, softmax over i (1024).
// logits = 10*cos - 5 in [-15, 5]: exp never overflows, skip the max pass.
__global__ void loss_kernel(const float* __restrict__ wp, const float* __restrict__ bp) {
    __shared__ float red[32];
    int r = blockIdx.x;
    int m = r >> 10;
    int j = r & (N_SPK - 1);
    const float* row = g_S + (size_t)j * NM + (size_t)m * N_SPK;
    float w = *wp, b = *bp;
    int t = threadIdx.x;

    float s = 0.0f;
    #pragma unroll
    for (int k = 0; k < 4; k++) s += expf(fmaf(w, row[t + k * 256], b));
    float gsum = block_reduce_sum(s, red);

    if (t == 0) {
        float lse  = logf(gsum);
        int   tgt  = r / M_UTT;                 // labels[r] = r // M
        float logp = fmaf(w, row[tgt], b) - lse;
        atomicAdd(&g_acc, (double)logp);
    }
}

__global__ void final_kernel(float* out) {
    out[0] = (float)(-g_acc / (double)NM);
}

// ---------------------------------------------------------------- launch
extern "C" void kernel_launch(void* const* d_in, const int* in_sizes, int n_in,
                              void* d_out, int out_size) {
    const float* emb = (const float*)d_in[0];
    const float* w   = (const float*)d_in[1];
    const float* b   = (const float*)d_in[2];
    float* out = (float*)d_out;

    static int smem_set = 0;
    if (!smem_set) {
        cudaFuncSetAttribute(gemm_mma_kernel, cudaFuncAttributeMaxDynamicSharedMemorySize,
                             SMEM_GEMM);
        smem_set = 1;
    }

    zero_kernel<<<1, 1>>>();
    norm_e_kernel<<<NM, 256>>>(emb);
    centroid_kernel<<<N_SPK, 256>>>(emb);
    dim3 ggrid(NM / 128, N_SPK / 128);   // 160 x 8
    gemm_mma_kernel<<<ggrid, 256, SMEM_GEMM>>>();
    loss_kernel<<<NM, 256>>>(w, b);
    final_kernel<<<1, 1>>>(out);
}

// round 5
// speedup vs baseline: 7.8616x; 1.4848x over previous
#include <cuda_runtime.h>
#include <cuda_bf16.h>
#include <cstdint>
#include <math.h>

#define N_SPK 1024
#define M_UTT 20
#define D_DIM 768
#define NM    (N_SPK * M_UTT)   // 20480

// ---- scratch (static device globals; no allocation in kernel_launch) ----
__device__ __nv_bfloat16 g_e[(size_t)NM * D_DIM];      // normalized e, row r = m*N + i
__device__ __nv_bfloat16 g_c[(size_t)N_SPK * D_DIM];   // normalized centroids
__device__ float         g_expsum[NM];                 // per-logit-row sum of exp
__device__ float         g_tgt[NM];                    // per-logit-row target logit
__device__ double        g_acc;                        // logp accumulator

// =================================================================== PTX utils
__device__ __forceinline__ uint32_t smem_u32(const void* p) {
    uint32_t a;
    asm("{ .reg .u64 t; cvta.to.shared.u64 t, %1; cvt.u32.u64 %0, t; }" : "=r"(a) : "l"(p));
    return a;
}
__device__ __forceinline__ void cp16(uint32_t saddr, const void* gptr) {
    asm volatile("cp.async.cg.shared.global [%0], [%1], 16;" :: "r"(saddr), "l"(gptr));
}
__device__ __forceinline__ void cp_commit() {
    asm volatile("cp.async.commit_group;" ::: "memory");
}
template <int N>
__device__ __forceinline__ void cp_wait() {
    asm volatile("cp.async.wait_group %0;" :: "n"(N) : "memory");
}
__device__ __forceinline__ void ldsm_x4(uint32_t& r0, uint32_t& r1, uint32_t& r2, uint32_t& r3,
                                        uint32_t addr) {
    asm volatile("ldmatrix.sync.aligned.m8n8.x4.shared.b16 {%0,%1,%2,%3}, [%4];"
                 : "=r"(r0), "=r"(r1), "=r"(r2), "=r"(r3) : "r"(addr));
}
__device__ __forceinline__ void mma16816(float* d, const uint32_t* a, const uint32_t* b) {
    asm volatile(
        "mma.sync.aligned.m16n8k16.row.col.f32.bf16.bf16.f32 "
        "{%0,%1,%2,%3}, {%4,%5,%6,%7}, {%8,%9}, {%0,%1,%2,%3};"
        : "+f"(d[0]), "+f"(d[1]), "+f"(d[2]), "+f"(d[3])
        : "r"(a[0]), "r"(a[1]), "r"(a[2]), "r"(a[3]), "r"(b[0]), "r"(b[1]));
}

// ---------------------------------------------------------------- reductions
__device__ __forceinline__ float block_reduce_sum(float v, float* red) {
    int t = threadIdx.x;
    #pragma unroll
    for (int o = 16; o; o >>= 1) v += __shfl_down_sync(0xffffffffu, v, o);
    if ((t & 31) == 0) red[t >> 5] = v;
    __syncthreads();
    if (t < 32) {
        float x = (t < (int)(blockDim.x >> 5)) ? red[t] : 0.0f;
        #pragma unroll
        for (int o = 16; o; o >>= 1) x += __shfl_down_sync(0xffffffffu, x, o);
        if (t == 0) red[0] = x;
    }
    __syncthreads();
    float r = red[0];
    __syncthreads();
    return r;
}

// ---------------------------------------------- fused normalize + centroid
// 1024 blocks (speaker i) x 256 threads; reads the 20 utterance rows once,
// emits 20 normalized g_e rows (r = m*N + i) and the normalized centroid.
__global__ void normcent_kernel(const float* __restrict__ emb) {
    __shared__ float red[32];
    const int i = blockIdx.x;
    const int t = threadIdx.x;
    const float* base = emb + (size_t)i * M_UTT * D_DIM;

    float cent[3] = {0.0f, 0.0f, 0.0f};
    #pragma unroll 1
    for (int m = 0; m < M_UTT; m++) {
        float v[3]; float ss = 0.0f;
        #pragma unroll
        for (int k = 0; k < 3; k++) {
            v[k] = base[(size_t)m * D_DIM + t + k * 256];
            cent[k] += v[k];
            ss += v[k] * v[k];
        }
        float tot = block_reduce_sum(ss, red);
        float inv = 1.0f / fmaxf(sqrtf(tot), 1e-8f);
        __nv_bfloat16* dst = g_e + (size_t)(m * N_SPK + i) * D_DIM;
        #pragma unroll
        for (int k = 0; k < 3; k++) dst[t + k * 256] = __float2bfloat16(v[k] * inv);
    }
    float ss = 0.0f;
    #pragma unroll
    for (int k = 0; k < 3; k++) { cent[k] *= (1.0f / M_UTT); ss += cent[k] * cent[k]; }
    float tot = block_reduce_sum(ss, red);
    float inv = 1.0f / fmaxf(sqrtf(tot), 1e-8f);
    __nv_bfloat16* dst = g_c + (size_t)i * D_DIM;
    #pragma unroll
    for (int k = 0; k < 3; k++) dst[t + k * 256] = __float2bfloat16(cent[k] * inv);
}

// ------------------------------------------------------------ mma.sync GEMM
// S = C (1024x768) * E^T (768x20480). CTA 128x128, BK=64, 8 warps (4m x 2n),
// warp tile 32x64. 128B smem rows, XOR-8 swizzle, 3-stage cp.async pipeline.
// Epilogue computes softmax partials directly (g_S never materialized).
#define BK        64
#define NKC       (D_DIM / BK)          // 12
#define A_BYTES   (128 * 128)           // 16 KB
#define STAGE_B   (2 * A_BYTES)         // 32 KB (A + B)
#define NSTAGE    3
#define SMEM_GEMM (NSTAGE * STAGE_B)    // 96 KB

__device__ __forceinline__ void load_chunk(uint32_t sb, int st, int kc, int jb, int nb, int tid) {
    uint32_t base = sb + st * STAGE_B;
    const int k0 = kc * BK;
    #pragma unroll
    for (int q = 0; q < 4; q++) {
        int idx = tid + q * 256;        // 0..1023
        int r = idx >> 3, c = idx & 7;
        cp16(base + r * 128 + ((c ^ (r & 7)) << 4),
             g_c + (size_t)(jb + r) * D_DIM + k0 + c * 8);
    }
    base += A_BYTES;
    #pragma unroll
    for (int q = 0; q < 4; q++) {
        int idx = tid + q * 256;
        int r = idx >> 3, c = idx & 7;
        cp16(base + r * 128 + ((c ^ (r & 7)) << 4),
             g_e + (size_t)(nb + r) * D_DIM + k0 + c * 8);
    }
}

__global__ void __launch_bounds__(256, 2)
gemm_mma_kernel(const float* __restrict__ wp, const float* __restrict__ bp) {
    extern __shared__ __align__(1024) char smc[];
    uint32_t sb = smem_u32(smc);
    const int tid  = threadIdx.x;
    const int lane = tid & 31;
    const int wid  = tid >> 5;
    const int wm   = wid & 3;           // 4 warps along m (32 rows each)
    const int wn   = wid >> 2;          // 2 warps along n (64 cols each)
    const int jb   = blockIdx.y * 128;
    const int nb   = blockIdx.x * 128;

    float acc[2][8][4];
    #pragma unroll
    for (int mf = 0; mf < 2; mf++)
        #pragma unroll
        for (int nf = 0; nf < 8; nf++)
            #pragma unroll
            for (int q = 0; q < 4; q++) acc[mf][nf][q] = 0.0f;

    // per-lane ldmatrix address components
    const int sw     = lane & 7;                          // swizzle key (= row & 7)
    const int a_row  = wm * 32 + (lane & 15);             // + mf*16
    const int a_hi   = lane >> 4;                         // A k-half selector
    const int b_row  = wn * 64 + (lane & 7) + ((lane >> 4) << 3);  // + nfp*16
    const int b_hi   = (lane >> 3) & 1;                   // B k-half selector

    load_chunk(sb, 0, 0, jb, nb, tid); cp_commit();
    load_chunk(sb, 1, 1, jb, nb, tid); cp_commit();

    #pragma unroll 1
    for (int kc = 0; kc < NKC; kc++) {
        if (kc == NKC - 1) cp_wait<0>(); else cp_wait<1>();
        __syncthreads();
        if (kc + 2 < NKC) {
            load_chunk(sb, (kc + 2) % NSTAGE, kc + 2, jb, nb, tid);
            cp_commit();
        }
        uint32_t Ab = sb + (kc % NSTAGE) * STAGE_B;
        uint32_t Bb = Ab + A_BYTES;
        #pragma unroll
        for (int ks = 0; ks < 4; ks++) {
            uint32_t a[2][4];
            #pragma unroll
            for (int mf = 0; mf < 2; mf++) {
                uint32_t addr = Ab + (a_row + mf * 16) * 128 + (((ks * 2 + a_hi) ^ sw) << 4);
                ldsm_x4(a[mf][0], a[mf][1], a[mf][2], a[mf][3], addr);
            }
            #pragma unroll
            for (int nfp = 0; nfp < 4; nfp++) {
                uint32_t b4[4];
                uint32_t addr = Bb + (b_row + nfp * 16) * 128 + (((ks * 2 + b_hi) ^ sw) << 4);
                ldsm_x4(b4[0], b4[1], b4[2], b4[3], addr);
                #pragma unroll
                for (int mf = 0; mf < 2; mf++) {
                    mma16816(acc[mf][2 * nfp + 0], a[mf], b4 + 0);
                    mma16816(acc[mf][2 * nfp + 1], a[mf], b4 + 2);
                }
            }
        }
    }

    // ---------------- fused softmax epilogue ----------------
    // This CTA covers rows j in [jb, jb+128), cols (m, i) with m = nb/1024,
    // i in [i0, i0+128). Softmax row index r = m*1024 + j.
    const float wv = *wp, bv = *bp;
    const int m_idx = nb >> 10;
    const int i0    = nb & 1023;

    #pragma unroll
    for (int mf = 0; mf < 2; mf++) {
        // exp partials over this warp's 64 cols; p0 for row half 0, p1 for half 1
        float p0 = 0.0f, p1 = 0.0f;
        #pragma unroll
        for (int nf = 0; nf < 8; nf++) {
            p0 += __expf(fmaf(wv, acc[mf][nf][0], bv)) + __expf(fmaf(wv, acc[mf][nf][1], bv));
            p1 += __expf(fmaf(wv, acc[mf][nf][2], bv)) + __expf(fmaf(wv, acc[mf][nf][3], bv));
        }
        p0 += __shfl_xor_sync(0xffffffffu, p0, 1);
        p0 += __shfl_xor_sync(0xffffffffu, p0, 2);
        p1 += __shfl_xor_sync(0xffffffffu, p1, 1);
        p1 += __shfl_xor_sync(0xffffffffu, p1, 2);
        int j0 = jb + wm * 32 + mf * 16 + (lane >> 2);   // row for half 0; half 1 is +8
        if ((lane & 3) == 0) {
            atomicAdd(&g_expsum[m_idx * N_SPK + j0],     p0);
            atomicAdd(&g_expsum[m_idx * N_SPK + j0 + 8], p1);
        }
        // target logit: row r's target col is i* = r / M_UTT; single owning lane writes
        #pragma unroll
        for (int half = 0; half < 2; half++) {
            int j = j0 + half * 8;
            int r = m_idx * N_SPK + j;
            int c = r / M_UTT - i0;
            if (c >= 0 && c < 128 && (c >> 6) == wn && ((c & 7) >> 1) == (lane & 3)) {
                int tnf = (c & 63) >> 3;
                #pragma unroll
                for (int nf = 0; nf < 8; nf++) {
                    if (nf == tnf) {
                        float v = (c & 1) ? acc[mf][nf][half * 2 + 1]
                                          : acc[mf][nf][half * 2 + 0];
                        g_tgt[r] = fmaf(wv, v, bv);
                    }
                }
            }
        }
    }
}

// ------------------------------------------------------------ loss pieces
__global__ void zero_kernel() {
    int idx = blockIdx.x * 1024 + threadIdx.x;
    g_expsum[idx] = 0.0f;
    if (idx == 0) g_acc = 0.0;
}

// 20 blocks x 1024 threads: loss partials over the 20480 logit rows
__global__ void loss_reduce_kernel() {
    __shared__ float red[32];
    int idx = blockIdx.x * 1024 + threadIdx.x;
    float v = g_tgt[idx] - logf(g_expsum[idx]);
    float s = block_reduce_sum(v, red);
    if (threadIdx.x == 0) atomicAdd(&g_acc, (double)s);
}

__global__ void final_kernel(float* out) {
    out[0] = (float)(-g_acc / (double)NM);
}

// ---------------------------------------------------------------- launch
extern "C" void kernel_launch(void* const* d_in, const int* in_sizes, int n_in,
                              void* d_out, int out_size) {
    const float* emb = (const float*)d_in[0];
    const float* w   = (const float*)d_in[1];
    const float* b   = (const float*)d_in[2];
    float* out = (float*)d_out;

    static int smem_set = 0;
    if (!smem_set) {
        cudaFuncSetAttribute(gemm_mma_kernel, cudaFuncAttributeMaxDynamicSharedMemorySize,
                             SMEM_GEMM);
        smem_set = 1;
    }

    zero_kernel<<<NM / 1024, 1024>>>();
    normcent_kernel<<<N_SPK, 256>>>(emb);
    dim3 ggrid(NM / 128, N_SPK / 128);   // 160 x 8
    gemm_mma_kernel<<<ggrid, 256, SMEM_GEMM>>>(w, b);
    loss_reduce_kernel<<<NM / 1024, 1024>>>();
    final_kernel<<<1, 1>>>(out);
}

// round 6
// speedup vs baseline: 8.6190x; 1.0963x over previous
#include <cuda_runtime.h>
#include <cuda_bf16.h>
#include <cstdint>
#include <math.h>

#define N_SPK 1024
#define M_UTT 20
#define D_DIM 768
#define NM    (N_SPK * M_UTT)   // 20480

// ---- scratch (static device globals; no allocation in kernel_launch) ----
__device__ __nv_bfloat16 g_e[(size_t)NM * D_DIM];      // normalized e, row r = m*N + i
__device__ __nv_bfloat16 g_c[(size_t)N_SPK * D_DIM];   // normalized centroids
__device__ float         g_expsum[NM];                 // per-logit-row sum of exp
__device__ float         g_tgt[NM];                    // per-logit-row target logit
__device__ double        g_acc;                        // logp accumulator

// =================================================================== PTX utils
__device__ __forceinline__ uint32_t smem_u32(const void* p) {
    uint32_t a;
    asm("{ .reg .u64 t; cvta.to.shared.u64 t, %1; cvt.u32.u64 %0, t; }" : "=r"(a) : "l"(p));
    return a;
}
__device__ __forceinline__ void cp16(uint32_t saddr, const void* gptr) {
    asm volatile("cp.async.cg.shared.global [%0], [%1], 16;" :: "r"(saddr), "l"(gptr));
}
__device__ __forceinline__ void cp_commit() {
    asm volatile("cp.async.commit_group;" ::: "memory");
}
template <int N>
__device__ __forceinline__ void cp_wait() {
    asm volatile("cp.async.wait_group %0;" :: "n"(N) : "memory");
}
__device__ __forceinline__ void ldsm_x4(uint32_t& r0, uint32_t& r1, uint32_t& r2, uint32_t& r3,
                                        uint32_t addr) {
    asm volatile("ldmatrix.sync.aligned.m8n8.x4.shared.b16 {%0,%1,%2,%3}, [%4];"
                 : "=r"(r0), "=r"(r1), "=r"(r2), "=r"(r3) : "r"(addr));
}
__device__ __forceinline__ void mma16816(float* d, const uint32_t* a, const uint32_t* b) {
    asm volatile(
        "mma.sync.aligned.m16n8k16.row.col.f32.bf16.bf16.f32 "
        "{%0,%1,%2,%3}, {%4,%5,%6,%7}, {%8,%9}, {%0,%1,%2,%3};"
        : "+f"(d[0]), "+f"(d[1]), "+f"(d[2]), "+f"(d[3])
        : "r"(a[0]), "r"(a[1]), "r"(a[2]), "r"(a[3]), "r"(b[0]), "r"(b[1]));
}

// ---------------------------------------------------------------- reductions
__device__ __forceinline__ float block_reduce_sum(float v, float* red) {
    int t = threadIdx.x;
    #pragma unroll
    for (int o = 16; o; o >>= 1) v += __shfl_down_sync(0xffffffffu, v, o);
    if ((t & 31) == 0) red[t >> 5] = v;
    __syncthreads();
    if (t < 32) {
        float x = (t < (int)(blockDim.x >> 5)) ? red[t] : 0.0f;
        #pragma unroll
        for (int o = 16; o; o >>= 1) x += __shfl_down_sync(0xffffffffu, x, o);
        if (t == 0) red[0] = x;
    }
    __syncthreads();
    float r = red[0];
    __syncthreads();
    return r;
}

// ---------------------------------------------- fused normalize + centroid
// 1024 blocks (speaker i) x 768 threads (24 warps; warps 0-19 own utterances).
// Warp m: lane reads 24 floats (6 float4), warp-reduce norm, writes bf16 row,
// stages raw values into smem; phase 2 sums the 20 rows per dim for the centroid.
#define NC_SMEM (M_UTT * D_DIM * 4 + 128)   // 61440 + red

__global__ void normcent_kernel(const float* __restrict__ emb) {
    extern __shared__ __align__(16) char nsm[];
    float* cent_s = reinterpret_cast<float*>(nsm);                  // [20][768]
    float* red    = reinterpret_cast<float*>(nsm + M_UTT * D_DIM * 4);

    const int i    = blockIdx.x;
    const int t    = threadIdx.x;
    const int wid  = t >> 5;
    const int lane = t & 31;

    if (wid < M_UTT) {
        const int m = wid;
        const float* src = emb + ((size_t)i * M_UTT + m) * D_DIM;
        float4 v[6];
        float ss = 0.0f;
        #pragma unroll
        for (int q = 0; q < 6; q++) {
            v[q] = *reinterpret_cast<const float4*>(src + lane * 4 + q * 128);
            ss += v[q].x * v[q].x + v[q].y * v[q].y + v[q].z * v[q].z + v[q].w * v[q].w;
        }
        #pragma unroll
        for (int o = 16; o; o >>= 1) ss += __shfl_xor_sync(0xffffffffu, ss, o);
        float inv = 1.0f / fmaxf(sqrtf(ss), 1e-8f);

        __nv_bfloat16* dst = g_e + (size_t)(m * N_SPK + i) * D_DIM;
        #pragma unroll
        for (int q = 0; q < 6; q++) {
            int off = lane * 4 + q * 128;
            // stage raw values for centroid
            *reinterpret_cast<float4*>(cent_s + m * D_DIM + off) = v[q];
            __nv_bfloat162 lo = __floats2bfloat162_rn(v[q].x * inv, v[q].y * inv);
            __nv_bfloat162 hi = __floats2bfloat162_rn(v[q].z * inv, v[q].w * inv);
            *reinterpret_cast<__nv_bfloat162*>(dst + off)     = lo;
            *reinterpret_cast<__nv_bfloat162*>(dst + off + 2) = hi;
        }
    }
    __syncthreads();

    // phase 2: thread t owns dim t
    float ds = 0.0f;
    #pragma unroll
    for (int m = 0; m < M_UTT; m++) ds += cent_s[m * D_DIM + t];
    ds *= (1.0f / M_UTT);
    cent_s[t] = ds;                       // visible after reduce's internal syncs
    float tot = block_reduce_sum(ds * ds, red);
    float inv = 1.0f / fmaxf(sqrtf(tot), 1e-8f);
    if (t < D_DIM / 2) {
        __nv_bfloat162 p = __floats2bfloat162_rn(cent_s[2 * t] * inv, cent_s[2 * t + 1] * inv);
        *reinterpret_cast<__nv_bfloat162*>(g_c + (size_t)i * D_DIM + 2 * t) = p;
    }
}

// ------------------------------------------------------------ mma.sync GEMM
// S = C (1024x768) * E^T (768x20480). CTA 128x128, BK=64, 4 warps (2m x 2n),
// warp tile 64x64. 128B smem rows, XOR-8 swizzle, 3-stage cp.async pipeline.
// Epilogue folds softmax partials directly (S never hits DRAM).
#define BK        64
#define NKC       (D_DIM / BK)          // 12
#define A_BYTES   (128 * 128)           // 16 KB
#define STAGE_B   (2 * A_BYTES)         // 32 KB (A + B)
#define NSTAGE    3
#define SMEM_GEMM (NSTAGE * STAGE_B)    // 96 KB

__device__ __forceinline__ void load_chunk(uint32_t sb, int st, int kc, int jb, int nb, int tid) {
    uint32_t base = sb + st * STAGE_B;
    const int k0 = kc * BK;
    #pragma unroll
    for (int q = 0; q < 8; q++) {
        int idx = tid + q * 128;        // 0..1023
        int r = idx >> 3, c = idx & 7;
        cp16(base + r * 128 + ((c ^ (r & 7)) << 4),
             g_c + (size_t)(jb + r) * D_DIM + k0 + c * 8);
    }
    base += A_BYTES;
    #pragma unroll
    for (int q = 0; q < 8; q++) {
        int idx = tid + q * 128;
        int r = idx >> 3, c = idx & 7;
        cp16(base + r * 128 + ((c ^ (r & 7)) << 4),
             g_e + (size_t)(nb + r) * D_DIM + k0 + c * 8);
    }
}

__global__ void __launch_bounds__(128, 2)
gemm_mma_kernel(const float* __restrict__ wp, const float* __restrict__ bp) {
    extern __shared__ __align__(1024) char smc[];
    uint32_t sb = smem_u32(smc);
    const int tid  = threadIdx.x;
    const int lane = tid & 31;
    const int wid  = tid >> 5;
    const int wm   = wid & 1;           // 2 warps along m (64 rows each)
    const int wn   = wid >> 1;          // 2 warps along n (64 cols each)
    const int jb   = blockIdx.y * 128;
    const int nb   = blockIdx.x * 128;

    float acc[4][8][4];
    #pragma unroll
    for (int mf = 0; mf < 4; mf++)
        #pragma unroll
        for (int nf = 0; nf < 8; nf++)
            #pragma unroll
            for (int q = 0; q < 4; q++) acc[mf][nf][q] = 0.0f;

    // per-lane ldmatrix address components (row&7 == lane&7 for both A and B)
    const int sw    = lane & 7;
    const int a_row = wm * 64 + (lane & 15);                       // + mf*16
    const int a_hi  = lane >> 4;
    const int b_row = wn * 64 + (lane & 7) + ((lane >> 4) << 3);   // + nfp*16
    const int b_hi  = (lane >> 3) & 1;

    load_chunk(sb, 0, 0, jb, nb, tid); cp_commit();
    load_chunk(sb, 1, 1, jb, nb, tid); cp_commit();

    #pragma unroll 1
    for (int kc = 0; kc < NKC; kc++) {
        if (kc == NKC - 1) cp_wait<0>(); else cp_wait<1>();
        __syncthreads();
        if (kc + 2 < NKC) {
            load_chunk(sb, (kc + 2) % NSTAGE, kc + 2, jb, nb, tid);
            cp_commit();
        }
        uint32_t Ab = sb + (kc % NSTAGE) * STAGE_B;
        uint32_t Bb = Ab + A_BYTES;
        #pragma unroll
        for (int ks = 0; ks < 4; ks++) {
            uint32_t a[4][4];
            #pragma unroll
            for (int mf = 0; mf < 4; mf++) {
                uint32_t addr = Ab + (a_row + mf * 16) * 128 + (((ks * 2 + a_hi) ^ sw) << 4);
                ldsm_x4(a[mf][0], a[mf][1], a[mf][2], a[mf][3], addr);
            }
            #pragma unroll
            for (int nfp = 0; nfp < 4; nfp++) {
                uint32_t b4[4];
                uint32_t addr = Bb + (b_row + nfp * 16) * 128 + (((ks * 2 + b_hi) ^ sw) << 4);
                ldsm_x4(b4[0], b4[1], b4[2], b4[3], addr);
                #pragma unroll
                for (int mf = 0; mf < 4; mf++) {
                    mma16816(acc[mf][2 * nfp + 0], a[mf], b4 + 0);
                    mma16816(acc[mf][2 * nfp + 1], a[mf], b4 + 2);
                }
            }
        }
    }

    // ---------------- fused softmax epilogue ----------------
    // rows j in [jb, jb+128), cols (m, i): m = nb/1024, i in [i0, i0+128).
    const float wv = *wp, bv = *bp;
    const int m_idx = nb >> 10;
    const int i0    = nb & 1023;

    #pragma unroll
    for (int mf = 0; mf < 4; mf++) {
        float p0 = 0.0f, p1 = 0.0f;
        #pragma unroll
        for (int nf = 0; nf < 8; nf++) {
            p0 += __expf(fmaf(wv, acc[mf][nf][0], bv)) + __expf(fmaf(wv, acc[mf][nf][1], bv));
            p1 += __expf(fmaf(wv, acc[mf][nf][2], bv)) + __expf(fmaf(wv, acc[mf][nf][3], bv));
        }
        p0 += __shfl_xor_sync(0xffffffffu, p0, 1);
        p0 += __shfl_xor_sync(0xffffffffu, p0, 2);
        p1 += __shfl_xor_sync(0xffffffffu, p1, 1);
        p1 += __shfl_xor_sync(0xffffffffu, p1, 2);
        int j0 = jb + wm * 64 + mf * 16 + (lane >> 2);   // half 0; half 1 is +8
        if ((lane & 3) == 0) {
            atomicAdd(&g_expsum[m_idx * N_SPK + j0],     p0);
            atomicAdd(&g_expsum[m_idx * N_SPK + j0 + 8], p1);
        }
        // target logit: row r's target col is i* = r / M_UTT
        #pragma unroll
        for (int half = 0; half < 2; half++) {
            int j = j0 + half * 8;
            int r = m_idx * N_SPK + j;
            int c = r / M_UTT - i0;
            if (c >= 0 && c < 128 && (c >> 6) == wn && ((c & 7) >> 1) == (lane & 3)) {
                int tnf = (c & 63) >> 3;
                #pragma unroll
                for (int nf = 0; nf < 8; nf++) {
                    if (nf == tnf) {
                        float v = (c & 1) ? acc[mf][nf][half * 2 + 1]
                                          : acc[mf][nf][half * 2 + 0];
                        g_tgt[r] = fmaf(wv, v, bv);
                    }
                }
            }
        }
    }
}

// ------------------------------------------------------------ loss pieces
__global__ void zero_kernel() {
    int idx = blockIdx.x * 256 + threadIdx.x;
    g_expsum[idx] = 0.0f;
    if (idx == 0) g_acc = 0.0;
}

// 80 blocks x 256 threads: loss partials over the 20480 logit rows
__global__ void loss_reduce_kernel() {
    __shared__ float red[32];
    int idx = blockIdx.x * 256 + threadIdx.x;
    float v = g_tgt[idx] - logf(g_expsum[idx]);
    float s = block_reduce_sum(v, red);
    if (threadIdx.x == 0) atomicAdd(&g_acc, (double)s);
}

__global__ void final_kernel(float* out) {
    out[0] = (float)(-g_acc / (double)NM);
}

// ---------------------------------------------------------------- launch
extern "C" void kernel_launch(void* const* d_in, const int* in_sizes, int n_in,
                              void* d_out, int out_size) {
    const float* emb = (const float*)d_in[0];
    const float* w   = (const float*)d_in[1];
    const float* b   = (const float*)d_in[2];
    float* out = (float*)d_out;

    static int smem_set = 0;
    if (!smem_set) {
        cudaFuncSetAttribute(gemm_mma_kernel, cudaFuncAttributeMaxDynamicSharedMemorySize,
                             SMEM_GEMM);
        cudaFuncSetAttribute(normcent_kernel, cudaFuncAttributeMaxDynamicSharedMemorySize,
                             NC_SMEM);
        smem_set = 1;
    }

    zero_kernel<<<NM / 256, 256>>>();
    normcent_kernel<<<N_SPK, 768, NC_SMEM>>>(emb);
    dim3 ggrid(NM / 128, N_SPK / 128);   // 160 x 8
    gemm_mma_kernel<<<ggrid, 128, SMEM_GEMM>>>(w, b);
    loss_reduce_kernel<<<NM / 256, 256>>>();
    final_kernel<<<1, 1>>>(out);
}